// round 2
// baseline (speedup 1.0000x reference)
#include <cuda_runtime.h>
#include <cstdint>
#include <cstddef>

// Problem dims
#define B_   16
#define S_   1024
#define D_   768
#define H_   384
#define G4   1536          // 4*H
#define M_   16384         // B*S

// ---------------- scratch (static device allocations, 256B aligned) ----------------
__device__ __align__(256) float g_xprojF[(size_t)M_ * G4];
__device__ __align__(256) float g_xprojB[(size_t)M_ * G4];
__device__ __align__(256) float g_lstm  [(size_t)M_ * 768];
__device__ __align__(256) float g_hcat  [(size_t)M_ * 768];
__device__ __align__(256) float g_h2    [(size_t)M_ * H_];
__device__ __align__(256) float g_mlp1  [(size_t)M_ * 256];
__device__ __align__(256) float g_mlp2  [(size_t)M_ * 96];
__device__ unsigned g_bar_cnt;   // zero-init
__device__ unsigned g_bar_gen;   // zero-init

// ---------------- generic GEMM: C = act(A[M,K] @ W[N,K]^T + bias) ----------------
// 128x128 tile, BK=16, 256 threads, 8x8 per thread. M multiple of 128, K multiple of 16.
template<int ACT>
__global__ __launch_bounds__(256) void gemm_bias_kernel(
    const float* __restrict__ A, const float* __restrict__ W,
    const float* __restrict__ bias, float* __restrict__ C,
    int M, int N, int K, int ldc)
{
    __shared__ float sA[16][132];
    __shared__ float sB[16][132];
    int tid = threadIdx.x;
    int m0 = blockIdx.y * 128;
    int n0 = blockIdx.x * 128;
    int tx = tid & 15, ty = tid >> 4;

    float acc[8][8];
#pragma unroll
    for (int i = 0; i < 8; i++)
#pragma unroll
        for (int j = 0; j < 8; j++) acc[i][j] = 0.f;

    for (int k0 = 0; k0 < K; k0 += 16) {
#pragma unroll
        for (int e = 0; e < 2; e++) {
            int f4 = tid + 256 * e;
            int r  = f4 >> 2;
            int c4 = (f4 & 3) << 2;
            float4 av = *(const float4*)(A + (size_t)(m0 + r) * K + k0 + c4);
            sA[c4 + 0][r] = av.x; sA[c4 + 1][r] = av.y;
            sA[c4 + 2][r] = av.z; sA[c4 + 3][r] = av.w;
            int n = n0 + r;
            float4 wv = make_float4(0.f, 0.f, 0.f, 0.f);
            if (n < N) wv = *(const float4*)(W + (size_t)n * K + k0 + c4);
            sB[c4 + 0][r] = wv.x; sB[c4 + 1][r] = wv.y;
            sB[c4 + 2][r] = wv.z; sB[c4 + 3][r] = wv.w;
        }
        __syncthreads();
#pragma unroll
        for (int kk = 0; kk < 16; kk++) {
            float a[8], b[8];
            *(float4*)&a[0] = *(const float4*)&sA[kk][ty * 8];
            *(float4*)&a[4] = *(const float4*)&sA[kk][ty * 8 + 4];
            *(float4*)&b[0] = *(const float4*)&sB[kk][tx * 8];
            *(float4*)&b[4] = *(const float4*)&sB[kk][tx * 8 + 4];
#pragma unroll
            for (int i = 0; i < 8; i++)
#pragma unroll
                for (int j = 0; j < 8; j++)
                    acc[i][j] = fmaf(a[i], b[j], acc[i][j]);
        }
        __syncthreads();
    }

#pragma unroll
    for (int i = 0; i < 8; i++) {
        int m = m0 + ty * 8 + i;
#pragma unroll
        for (int j = 0; j < 8; j++) {
            int n = n0 + tx * 8 + j;
            if (n < N) {
                float v = acc[i][j] + bias[n];
                if (ACT) v = fmaxf(v, 0.f);
                C[(size_t)m * ldc + n] = v;
            }
        }
    }
}

// ---------------- LSTM recurrent scan (both directions, persistent) ----------------
#define NU    6
#define RW    24      // 4*NU gate rows per CTA
#define KSPL  8
#define KCH   48      // 384/8
#define WPAD  392     // padded k-stride for smem rows
#define NCTA  128

__device__ __forceinline__ float sigm_(float x) { return 1.f / (1.f + __expf(-x)); }
__device__ __forceinline__ float tanh_(float x) {
    float t = __expf(-2.f * fabsf(x));
    float r = (1.f - t) / (1.f + t);
    return x < 0.f ? -r : r;
}

__global__ __launch_bounds__(128, 1) void lstm_scan_kernel(
    const float* __restrict__ xpF, const float* __restrict__ xpB,
    const float* __restrict__ WhhF, const float* __restrict__ WhhB,
    float* __restrict__ out /* [B,S,768]: fwd cols 0:384, bwd 384:768 */)
{
    extern __shared__ float sm[];
    float* s_w = sm;                        // RW * WPAD
    float* s_h = s_w + RW * WPAD;           // 16 * WPAD
    float* s_p = s_h + 16 * WPAD;           // KSPL * 16 * RW
    float* s_c = s_p + KSPL * 16 * RW;      // 16 * NU

    int tid = threadIdx.x;
    int dir = blockIdx.x >> 6;
    int cg  = blockIdx.x & 63;
    int u0  = cg * NU;
    const float* Whh = dir ? WhhB : WhhF;
    const float* xp  = dir ? xpB  : xpF;

    // preload Whh slice (rows: gate-major g*H_ + u0+u -> local g*NU+u)
    for (int idx = tid; idx < RW * (H_ / 4); idx += 128) {
        int r  = idx / (H_ / 4);
        int c4 = (idx % (H_ / 4)) * 4;
        int g = r / NU, u = r % NU;
        float4 w = *(const float4*)(Whh + (size_t)(g * H_ + u0 + u) * H_ + c4);
        *(float4*)&s_w[r * WPAD + c4] = w;
    }
    for (int idx = tid; idx < 16 * NU; idx += 128) s_c[idx] = 0.f;

    int tile = tid >> 3;              // 0..15
    int kq   = tid & 7;               // split-k index
    int b0   = (tile >> 2) << 2;      // {0,4,8,12}
    int r0   = (tile & 3) * NU;       // {0,6,12,18}
    int kbeg = kq * KCH;

    int cb = tid / NU, cu = tid % NU; // gate-combine role (tid < 96)

    for (int step = 0; step < S_; step++) {
        int tt = dir ? (S_ - 1 - step) : step;

        // prefetch xproj for this step's gate combine
        float xpre[4] = {0.f, 0.f, 0.f, 0.f};
        if (tid < 16 * NU) {
            size_t base = ((size_t)(cb * S_ + tt)) * G4 + u0 + cu;
#pragma unroll
            for (int g = 0; g < 4; g++) xpre[g] = xp[base + g * H_];
        }

        // load h_prev into smem (L2 loads: written by other SMs last step)
        if (step == 0) {
            for (int idx = tid; idx < 16 * (H_ / 4); idx += 128) {
                int b = idx / (H_ / 4); int c4 = (idx % (H_ / 4)) * 4;
                *(float4*)&s_h[b * WPAD + c4] = make_float4(0.f, 0.f, 0.f, 0.f);
            }
        } else {
            int tp = dir ? (tt + 1) : (tt - 1);
            for (int idx = tid; idx < 16 * (H_ / 4); idx += 128) {
                int b = idx / (H_ / 4); int c4 = (idx % (H_ / 4)) * 4;
                const float4* src = (const float4*)(out + ((size_t)(b * S_ + tp)) * 768 + dir * H_ + c4);
                *(float4*)&s_h[b * WPAD + c4] = __ldcg(src);
            }
        }
        __syncthreads();

        // mini-GEMM: acc[4b][6r] over k in [kbeg, kbeg+48)
        float acc[4][NU];
#pragma unroll
        for (int i = 0; i < 4; i++)
#pragma unroll
            for (int j = 0; j < NU; j++) acc[i][j] = 0.f;

#pragma unroll 2
        for (int k = kbeg; k < kbeg + KCH; k += 4) {
            float4 h4[4], w4[NU];
#pragma unroll
            for (int i = 0; i < 4; i++) h4[i] = *(const float4*)&s_h[(b0 + i) * WPAD + k];
#pragma unroll
            for (int j = 0; j < NU; j++) w4[j] = *(const float4*)&s_w[(r0 + j) * WPAD + k];
#pragma unroll
            for (int i = 0; i < 4; i++)
#pragma unroll
                for (int j = 0; j < NU; j++) {
                    acc[i][j] = fmaf(h4[i].x, w4[j].x, acc[i][j]);
                    acc[i][j] = fmaf(h4[i].y, w4[j].y, acc[i][j]);
                    acc[i][j] = fmaf(h4[i].z, w4[j].z, acc[i][j]);
                    acc[i][j] = fmaf(h4[i].w, w4[j].w, acc[i][j]);
                }
        }
#pragma unroll
        for (int i = 0; i < 4; i++)
#pragma unroll
            for (int j = 0; j < NU; j++)
                s_p[(kq * 16 + b0 + i) * RW + r0 + j] = acc[i][j];
        __syncthreads();

        // gate combine: one thread per (batch, unit)
        if (tid < 16 * NU) {
            float gate[4];
#pragma unroll
            for (int g = 0; g < 4; g++) {
                float s = xpre[g];
#pragma unroll
                for (int q = 0; q < KSPL; q++) s += s_p[(q * 16 + cb) * RW + g * NU + cu];
                gate[g] = s;
            }
            float c = sigm_(gate[1]) * s_c[cb * NU + cu] + sigm_(gate[0]) * tanh_(gate[2]);
            s_c[cb * NU + cu] = c;
            float h = sigm_(gate[3]) * tanh_(c);
            out[((size_t)(cb * S_ + tt)) * 768 + dir * H_ + u0 + cu] = h;
        }

        // release: every thread fences its own stores, then grid barrier
        __threadfence();
        __syncthreads();
        if (tid == 0) {
            unsigned g = atomicAdd(&g_bar_gen, 0u);
            if (atomicAdd(&g_bar_cnt, 1u) == (unsigned)(NCTA - 1)) {
                atomicExch(&g_bar_cnt, 0u);
                __threadfence();
                atomicAdd(&g_bar_gen, 1u);
            } else {
                while (atomicAdd(&g_bar_gen, 0u) == g) __nanosleep(64);
            }
        }
        __syncthreads();
        __threadfence();
    }
}

// ---------------- windowed attention ----------------
// score(i,j) = s1[i] + s2[j] + (h_i*w3)@h_j + b ; s1[i]+b is softmax-invariant.
__global__ __launch_bounds__(256) void attn_kernel(
    float* __restrict__ hcat, const float* __restrict__ attnW,
    const int* __restrict__ wsp)
{
    int gw   = (int)((blockIdx.x * blockDim.x + threadIdx.x) >> 5);
    int lane = threadIdx.x & 31;
    if (gw >= M_) return;
    int b = gw >> 10, i = gw & 1023;
    int Wn = wsp ? *wsp : 32;
    if (Wn < 0) Wn = 0;
    if (Wn > S_) Wn = S_;

    const float* w2 = attnW + H_;
    const float* w3 = attnW + 2 * H_;
    const float* hi = hcat + (size_t)gw * 768;

    float v[12], a[12];
#pragma unroll
    for (int q = 0; q < 12; q++) {
        int k = q * 32 + lane;
        v[q] = w2[k] + hi[k] * w3[k];
        a[q] = 0.f;
    }
    float m = -1e30f, Z = 0.f;
    int jlo = i - Wn; if (jlo < 0) jlo = 0;
    int jhi = i + Wn; if (jhi > S_ - 1) jhi = S_ - 1;

    for (int j = jlo; j <= jhi; j++) {
        const float* hj = hcat + ((size_t)(b * S_ + j)) * 768;
        float hq[12];
        float s = 0.f;
#pragma unroll
        for (int q = 0; q < 12; q++) {
            hq[q] = hj[q * 32 + lane];
            s = fmaf(v[q], hq[q], s);
        }
#pragma unroll
        for (int o = 16; o; o >>= 1) s += __shfl_xor_sync(0xffffffffu, s, o);
        float mn = fmaxf(m, s);
        float r  = __expf(m - mn);
        float e  = __expf(s - mn);
        Z = Z * r + e;
#pragma unroll
        for (int q = 0; q < 12; q++) a[q] = a[q] * r + e * hq[q];
        m = mn;
    }
    float inv = 1.f / Z;
#pragma unroll
    for (int q = 0; q < 12; q++)
        hcat[(size_t)gw * 768 + H_ + q * 32 + lane] = a[q] * inv;
}

// ---------------- final gemv: out[m] = y2[m,:96] @ W3 + b3 ----------------
__global__ __launch_bounds__(256) void gemv_kernel(
    const float* __restrict__ A, const float* __restrict__ w,
    const float* __restrict__ b, float* __restrict__ out)
{
    int gw   = (int)((blockIdx.x * blockDim.x + threadIdx.x) >> 5);
    int lane = threadIdx.x & 31;
    if (gw >= M_) return;
    float s = 0.f;
#pragma unroll
    for (int k = lane; k < 96; k += 32) s = fmaf(A[(size_t)gw * 96 + k], w[k], s);
#pragma unroll
    for (int o = 16; o; o >>= 1) s += __shfl_xor_sync(0xffffffffu, s, o);
    if (lane == 0) out[gw] = s + b[0];
}

// ---------------- host: size-based input resolution ----------------
static int pick_by_size(const int* sizes, int n, int want, unsigned char* used)
{
    for (int i = 0; i < n; i++) {
        if (!used[i] && sizes[i] == want) { used[i] = 1; return i; }
    }
    return -1;
}

extern "C" void kernel_launch(void* const* d_in, const int* in_sizes, int n_in,
                              void* d_out, int out_size)
{
    // Resolve inputs by element count (robust to ordering surprises).
    // Expected counts:
    //   x=12582912, Wih=1179648(x4), Whh=589824(x4), b=1536(x4),
    //   fc1_W=294912, fc1_b=384, attn_W=1152, attn_b=1,
    //   l2_W1=98304, l2_b1=256, l2_W2=24576, l2_b2=96, l2_W3=96, l2_b3=1,
    //   window_size=1
    unsigned char used[64];
    for (int i = 0; i < 64; i++) used[i] = 0;
    int ix[24];
    ix[0]  = pick_by_size(in_sizes, n_in, 12582912, used);   // x
    ix[1]  = pick_by_size(in_sizes, n_in, 1179648,  used);   // l1_Wih_f
    ix[2]  = pick_by_size(in_sizes, n_in, 589824,   used);   // l1_Whh_f
    ix[3]  = pick_by_size(in_sizes, n_in, 1536,     used);   // l1_b_f
    ix[4]  = pick_by_size(in_sizes, n_in, 1179648,  used);   // l1_Wih_b
    ix[5]  = pick_by_size(in_sizes, n_in, 589824,   used);   // l1_Whh_b
    ix[6]  = pick_by_size(in_sizes, n_in, 1536,     used);   // l1_b_b
    ix[7]  = pick_by_size(in_sizes, n_in, 294912,   used);   // fc1_W
    ix[8]  = pick_by_size(in_sizes, n_in, 384,      used);   // fc1_b
    ix[9]  = pick_by_size(in_sizes, n_in, 1152,     used);   // attn_W
    ix[10] = pick_by_size(in_sizes, n_in, 1,        used);   // attn_b (unused)
    ix[11] = pick_by_size(in_sizes, n_in, 1179648,  used);   // l2_Wih_f
    ix[12] = pick_by_size(in_sizes, n_in, 589824,   used);   // l2_Whh_f
    ix[13] = pick_by_size(in_sizes, n_in, 1536,     used);   // l2_b_f
    ix[14] = pick_by_size(in_sizes, n_in, 1179648,  used);   // l2_Wih_b
    ix[15] = pick_by_size(in_sizes, n_in, 589824,   used);   // l2_Whh_b
    ix[16] = pick_by_size(in_sizes, n_in, 1536,     used);   // l2_b_b
    ix[17] = pick_by_size(in_sizes, n_in, 98304,    used);   // l2_W1
    ix[18] = pick_by_size(in_sizes, n_in, 256,      used);   // l2_b1
    ix[19] = pick_by_size(in_sizes, n_in, 24576,    used);   // l2_W2
    ix[20] = pick_by_size(in_sizes, n_in, 96,       used);   // l2_b2
    ix[21] = pick_by_size(in_sizes, n_in, 96,       used);   // l2_W3
    ix[22] = pick_by_size(in_sizes, n_in, 1,        used);   // l2_b3
    ix[23] = pick_by_size(in_sizes, n_in, 1,        used);   // window_size

    // Fall back to positional order if size matching failed for any mandatory input.
    bool ok = true;
    for (int i = 0; i < 23; i++) if (ix[i] < 0) ok = false;
    if (!ok) {
        for (int i = 0; i < 24; i++) ix[i] = (i < n_in) ? i : -1;
    }

    const float* x      = (const float*)d_in[ix[0]];
    const float* l1Wihf = (const float*)d_in[ix[1]];
    const float* l1Whhf = (const float*)d_in[ix[2]];
    const float* l1bf   = (const float*)d_in[ix[3]];
    const float* l1Wihb = (const float*)d_in[ix[4]];
    const float* l1Whhb = (const float*)d_in[ix[5]];
    const float* l1bb   = (const float*)d_in[ix[6]];
    const float* fc1W   = (const float*)d_in[ix[7]];
    const float* fc1b   = (const float*)d_in[ix[8]];
    const float* attnW  = (const float*)d_in[ix[9]];
    const float* l2Wihf = (const float*)d_in[ix[11]];
    const float* l2Whhf = (const float*)d_in[ix[12]];
    const float* l2bf   = (const float*)d_in[ix[13]];
    const float* l2Wihb = (const float*)d_in[ix[14]];
    const float* l2Whhb = (const float*)d_in[ix[15]];
    const float* l2bb   = (const float*)d_in[ix[16]];
    const float* W1     = (const float*)d_in[ix[17]];
    const float* b1     = (const float*)d_in[ix[18]];
    const float* W2     = (const float*)d_in[ix[19]];
    const float* b2     = (const float*)d_in[ix[20]];
    const float* W3     = (const float*)d_in[ix[21]];
    const float* b3     = (const float*)d_in[ix[22]];
    const int*   wsp    = (ix[23] >= 0) ? (const int*)d_in[ix[23]] : nullptr;

    float *xpF, *xpB, *lstm, *hcat, *h2, *mlp1, *mlp2;
    cudaGetSymbolAddress((void**)&xpF,  g_xprojF);
    cudaGetSymbolAddress((void**)&xpB,  g_xprojB);
    cudaGetSymbolAddress((void**)&lstm, g_lstm);
    cudaGetSymbolAddress((void**)&hcat, g_hcat);
    cudaGetSymbolAddress((void**)&h2,   g_h2);
    cudaGetSymbolAddress((void**)&mlp1, g_mlp1);
    cudaGetSymbolAddress((void**)&mlp2, g_mlp2);

    size_t lsm = (size_t)(RW * WPAD + 16 * WPAD + KSPL * 16 * RW + 16 * NU) * sizeof(float);
    cudaFuncSetAttribute(lstm_scan_kernel,
                         cudaFuncAttributeMaxDynamicSharedMemorySize, (int)lsm);

    // ---- layer 1 ----
    gemm_bias_kernel<0><<<dim3(G4 / 128, M_ / 128), 256>>>(x, l1Wihf, l1bf, xpF, M_, G4, D_, G4);
    gemm_bias_kernel<0><<<dim3(G4 / 128, M_ / 128), 256>>>(x, l1Wihb, l1bb, xpB, M_, G4, D_, G4);
    lstm_scan_kernel<<<NCTA, 128, lsm>>>(xpF, xpB, l1Whhf, l1Whhb, lstm);

    // fc1 -> h (stored in first half of hcat, ldc=768)
    gemm_bias_kernel<0><<<dim3(3, M_ / 128), 256>>>(lstm, fc1W, fc1b, hcat, M_, H_, 768, 768);

    // windowed attention -> second half of hcat
    attn_kernel<<<M_ / 8, 256>>>(hcat, attnW, wsp);

    // ---- layer 2 ----
    gemm_bias_kernel<0><<<dim3(G4 / 128, M_ / 128), 256>>>(hcat, l2Wihf, l2bf, xpF, M_, G4, 768, G4);
    gemm_bias_kernel<0><<<dim3(G4 / 128, M_ / 128), 256>>>(hcat, l2Wihb, l2bb, xpB, M_, G4, 768, G4);
    lstm_scan_kernel<<<NCTA, 128, lsm>>>(xpF, xpB, l2Whhf, l2Whhb, lstm);

    // fc1 again -> h2
    gemm_bias_kernel<0><<<dim3(3, M_ / 128), 256>>>(lstm, fc1W, fc1b, h2, M_, H_, 768, H_);

    // MLP head
    gemm_bias_kernel<1><<<dim3(2, M_ / 128), 256>>>(h2,   W1, b1, mlp1, M_, 256, H_,  256);
    gemm_bias_kernel<1><<<dim3(1, M_ / 128), 256>>>(mlp1, W2, b2, mlp2, M_, 96,  256, 96);
    gemv_kernel<<<M_ / 8, 256>>>(mlp2, W3, b3, (float*)d_out);
}

// round 3
// speedup vs baseline: 1.0649x; 1.0649x over previous
#include <cuda_runtime.h>
#include <cstdint>
#include <cstddef>

// Problem dims
#define B_   16
#define S_   1024
#define D_   768
#define H_   384
#define G4   1536          // 4*H
#define M_   16384         // B*S

// ---------------- scratch (static device allocations, 256B aligned) ----------------
__device__ __align__(256) float g_xprojF[(size_t)M_ * G4];
__device__ __align__(256) float g_xprojB[(size_t)M_ * G4];
__device__ __align__(256) float g_lstm  [(size_t)M_ * 768];
__device__ __align__(256) float g_hcat  [(size_t)M_ * 768];
__device__ __align__(256) float g_h2    [(size_t)M_ * H_];
__device__ __align__(256) float g_mlp1  [(size_t)M_ * 256];
__device__ __align__(256) float g_mlp2  [(size_t)M_ * 96];
// dataflow flags: 128 producers, padded to 32B stride to spread L2 lines
__device__ __align__(256) unsigned g_flag[128 * 8];

// ---------------- generic GEMM: C = act(A[M,K] @ W[N,K]^T + bias) ----------------
// 128x128 tile, BK=16, 256 threads, 8x8 per thread. M multiple of 128, K multiple of 16.
template<int ACT>
__global__ __launch_bounds__(256, 2) void gemm_bias_kernel(
    const float* __restrict__ A, const float* __restrict__ W,
    const float* __restrict__ bias, float* __restrict__ C,
    int M, int N, int K, int ldc)
{
    __shared__ float sA[16][132];
    __shared__ float sB[16][132];
    int tid = threadIdx.x;
    int m0 = blockIdx.y * 128;
    int n0 = blockIdx.x * 128;
    int tx = tid & 15, ty = tid >> 4;

    float acc[8][8];
#pragma unroll
    for (int i = 0; i < 8; i++)
#pragma unroll
        for (int j = 0; j < 8; j++) acc[i][j] = 0.f;

    for (int k0 = 0; k0 < K; k0 += 16) {
#pragma unroll
        for (int e = 0; e < 2; e++) {
            int f4 = tid + 256 * e;
            int r  = f4 >> 2;
            int c4 = (f4 & 3) << 2;
            float4 av = *(const float4*)(A + (size_t)(m0 + r) * K + k0 + c4);
            sA[c4 + 0][r] = av.x; sA[c4 + 1][r] = av.y;
            sA[c4 + 2][r] = av.z; sA[c4 + 3][r] = av.w;
            int n = n0 + r;
            float4 wv = make_float4(0.f, 0.f, 0.f, 0.f);
            if (n < N) wv = *(const float4*)(W + (size_t)n * K + k0 + c4);
            sB[c4 + 0][r] = wv.x; sB[c4 + 1][r] = wv.y;
            sB[c4 + 2][r] = wv.z; sB[c4 + 3][r] = wv.w;
        }
        __syncthreads();
#pragma unroll
        for (int kk = 0; kk < 16; kk++) {
            float a[8], b[8];
            *(float4*)&a[0] = *(const float4*)&sA[kk][ty * 8];
            *(float4*)&a[4] = *(const float4*)&sA[kk][ty * 8 + 4];
            *(float4*)&b[0] = *(const float4*)&sB[kk][tx * 8];
            *(float4*)&b[4] = *(const float4*)&sB[kk][tx * 8 + 4];
#pragma unroll
            for (int i = 0; i < 8; i++)
#pragma unroll
                for (int j = 0; j < 8; j++)
                    acc[i][j] = fmaf(a[i], b[j], acc[i][j]);
        }
        __syncthreads();
    }

#pragma unroll
    for (int i = 0; i < 8; i++) {
        int m = m0 + ty * 8 + i;
#pragma unroll
        for (int j = 0; j < 8; j++) {
            int n = n0 + tx * 8 + j;
            if (n < N) {
                float v = acc[i][j] + bias[n];
                if (ACT) v = fmaxf(v, 0.f);
                C[(size_t)m * ldc + n] = v;
            }
        }
    }
}

// ---------------- LSTM recurrent scan (both directions, persistent) ----------------
// 128 CTAs x 256 threads: dir = cta>>6, group = cta&63, each group owns NU=6 units.
// Sync via per-producer dataflow flags (same-direction only), no central barrier.
#define NU    6
#define RW    24      // 4*NU gate rows per CTA
#define KSPL  16
#define KCH   24      // 384/16
#define WPAD  392     // padded k-stride for smem rows
#define NCTA  128
#define TPB   256

__device__ __forceinline__ float sigm_(float x) { return 1.f / (1.f + __expf(-x)); }
__device__ __forceinline__ float tanh_(float x) {
    float t = __expf(-2.f * fabsf(x));
    float r = (1.f - t) / (1.f + t);
    return x < 0.f ? -r : r;
}

__global__ void flags_zero_kernel()
{
    g_flag[threadIdx.x * 8] = 0u;
}

__global__ __launch_bounds__(TPB, 1) void lstm_scan_kernel(
    const float* __restrict__ xpF, const float* __restrict__ xpB,
    const float* __restrict__ WhhF, const float* __restrict__ WhhB,
    float* __restrict__ out /* [B,S,768]: fwd cols 0:384, bwd 384:768 */)
{
    extern __shared__ float sm[];
    float* s_w = sm;                        // RW * WPAD
    float* s_h = s_w + RW * WPAD;           // 16 * WPAD
    float* s_p = s_h + 16 * WPAD;           // KSPL * 16 * RW
    float* s_c = s_p + KSPL * 16 * RW;      // 16 * NU

    int tid = threadIdx.x;
    int dir = blockIdx.x >> 6;
    int cg  = blockIdx.x & 63;
    int u0  = cg * NU;
    const float* Whh = dir ? WhhB : WhhF;
    const float* xp  = dir ? xpB  : xpF;

    // preload Whh slice (rows: gate-major g*H_ + u0+u -> local g*NU+u)
    for (int idx = tid; idx < RW * (H_ / 4); idx += TPB) {
        int r  = idx / (H_ / 4);
        int c4 = (idx % (H_ / 4)) * 4;
        int g = r / NU, u = r % NU;
        float4 w = *(const float4*)(Whh + (size_t)(g * H_ + u0 + u) * H_ + c4);
        *(float4*)&s_w[r * WPAD + c4] = w;
    }
    if (tid < 16 * NU) s_c[tid] = 0.f;

    int tile = tid >> 4;              // 0..15
    int kq   = tid & 15;              // split-k index
    int b0   = (tile >> 2) << 2;      // {0,4,8,12}
    int r0   = (tile & 3) * NU;       // {0,6,12,18}
    int kbeg = kq * KCH;

    int cb = tid / NU, cu = tid % NU; // gate-combine role (tid < 96)

    volatile unsigned* myflag = &g_flag[(dir * 64 + cg) * 8];

    for (int step = 0; step < S_; step++) {
        int tt = dir ? (S_ - 1 - step) : step;

        // prefetch xproj for this step's gate combine
        float xpre[4] = {0.f, 0.f, 0.f, 0.f};
        if (tid < 16 * NU) {
            size_t base = ((size_t)(cb * S_ + tt)) * G4 + u0 + cu;
#pragma unroll
            for (int g = 0; g < 4; g++) xpre[g] = xp[base + g * H_];
        }

        if (step == 0) {
            for (int idx = tid; idx < 16 * (H_ / 4); idx += TPB) {
                int b = idx / (H_ / 4); int c4 = (idx % (H_ / 4)) * 4;
                *(float4*)&s_h[b * WPAD + c4] = make_float4(0.f, 0.f, 0.f, 0.f);
            }
            __syncthreads();
        } else {
            // wait for all 64 same-direction producers to publish step-1
            if (tid < 64) {
                volatile unsigned* f = &g_flag[(dir * 64 + tid) * 8];
                unsigned target = (unsigned)step;
                while (*f < target) __nanosleep(32);
            }
            __syncthreads();
            __threadfence();
            int tp = dir ? (tt + 1) : (tt - 1);
            for (int idx = tid; idx < 16 * (H_ / 4); idx += TPB) {
                int b = idx / (H_ / 4); int c4 = (idx % (H_ / 4)) * 4;
                const float4* src = (const float4*)(out + ((size_t)(b * S_ + tp)) * 768 + dir * H_ + c4);
                *(float4*)&s_h[b * WPAD + c4] = __ldcg(src);
            }
            __syncthreads();
        }

        // mini-GEMM: acc[4b][6r] over k in [kbeg, kbeg+24)
        float acc[4][NU];
#pragma unroll
        for (int i = 0; i < 4; i++)
#pragma unroll
            for (int j = 0; j < NU; j++) acc[i][j] = 0.f;

#pragma unroll
        for (int k = kbeg; k < kbeg + KCH; k += 4) {
            float4 h4[4], w4[NU];
#pragma unroll
            for (int i = 0; i < 4; i++) h4[i] = *(const float4*)&s_h[(b0 + i) * WPAD + k];
#pragma unroll
            for (int j = 0; j < NU; j++) w4[j] = *(const float4*)&s_w[(r0 + j) * WPAD + k];
#pragma unroll
            for (int i = 0; i < 4; i++)
#pragma unroll
                for (int j = 0; j < NU; j++) {
                    acc[i][j] = fmaf(h4[i].x, w4[j].x, acc[i][j]);
                    acc[i][j] = fmaf(h4[i].y, w4[j].y, acc[i][j]);
                    acc[i][j] = fmaf(h4[i].z, w4[j].z, acc[i][j]);
                    acc[i][j] = fmaf(h4[i].w, w4[j].w, acc[i][j]);
                }
        }
#pragma unroll
        for (int i = 0; i < 4; i++)
#pragma unroll
            for (int j = 0; j < NU; j++)
                s_p[(kq * 16 + b0 + i) * RW + r0 + j] = acc[i][j];
        __syncthreads();

        // gate combine: one thread per (batch, unit); write h to global (L2)
        if (tid < 16 * NU) {
            float gate[4];
#pragma unroll
            for (int g = 0; g < 4; g++) {
                float s = xpre[g];
#pragma unroll
                for (int q = 0; q < KSPL; q++) s += s_p[(q * 16 + cb) * RW + g * NU + cu];
                gate[g] = s;
            }
            float c = sigm_(gate[1]) * s_c[cb * NU + cu] + sigm_(gate[0]) * tanh_(gate[2]);
            s_c[cb * NU + cu] = c;
            float h = sigm_(gate[3]) * tanh_(c);
            __stcg(out + ((size_t)(cb * S_ + tt)) * 768 + dir * H_ + u0 + cu, h);
        }

        // publish: block-wide join, then release-fence + flag store by tid0
        __syncthreads();
        if (tid == 0) {
            __threadfence();
            *myflag = (unsigned)(step + 1);
        }
    }
}

// ---------------- windowed attention ----------------
// score(i,j) = s1[i] + s2[j] + (h_i*w3)@h_j + b ; s1[i]+b is softmax-invariant.
__global__ __launch_bounds__(256) void attn_kernel(
    float* __restrict__ hcat, const float* __restrict__ attnW,
    const int* __restrict__ wsp)
{
    int gw   = (int)((blockIdx.x * blockDim.x + threadIdx.x) >> 5);
    int lane = threadIdx.x & 31;
    if (gw >= M_) return;
    int b = gw >> 10, i = gw & 1023;
    int Wn = wsp ? *wsp : 32;
    if (Wn < 0) Wn = 0;
    if (Wn > S_) Wn = S_;

    const float* w2 = attnW + H_;
    const float* w3 = attnW + 2 * H_;
    const float* hi = hcat + (size_t)gw * 768;

    float v[12], a[12];
#pragma unroll
    for (int q = 0; q < 12; q++) {
        int k = q * 32 + lane;
        v[q] = w2[k] + hi[k] * w3[k];
        a[q] = 0.f;
    }
    float m = -1e30f, Z = 0.f;
    int jlo = i - Wn; if (jlo < 0) jlo = 0;
    int jhi = i + Wn; if (jhi > S_ - 1) jhi = S_ - 1;

    for (int j = jlo; j <= jhi; j++) {
        const float* hj = hcat + ((size_t)(b * S_ + j)) * 768;
        float hq[12];
        float s = 0.f;
#pragma unroll
        for (int q = 0; q < 12; q++) {
            hq[q] = hj[q * 32 + lane];
            s = fmaf(v[q], hq[q], s);
        }
#pragma unroll
        for (int o = 16; o; o >>= 1) s += __shfl_xor_sync(0xffffffffu, s, o);
        float mn = fmaxf(m, s);
        float r  = __expf(m - mn);
        float e  = __expf(s - mn);
        Z = Z * r + e;
#pragma unroll
        for (int q = 0; q < 12; q++) a[q] = a[q] * r + e * hq[q];
        m = mn;
    }
    float inv = 1.f / Z;
#pragma unroll
    for (int q = 0; q < 12; q++)
        hcat[(size_t)gw * 768 + H_ + q * 32 + lane] = a[q] * inv;
}

// ---------------- final gemv: out[m] = y2[m,:96] @ W3 + b3 ----------------
__global__ __launch_bounds__(256) void gemv_kernel(
    const float* __restrict__ A, const float* __restrict__ w,
    const float* __restrict__ b, float* __restrict__ out)
{
    int gw   = (int)((blockIdx.x * blockDim.x + threadIdx.x) >> 5);
    int lane = threadIdx.x & 31;
    if (gw >= M_) return;
    float s = 0.f;
#pragma unroll
    for (int k = lane; k < 96; k += 32) s = fmaf(A[(size_t)gw * 96 + k], w[k], s);
#pragma unroll
    for (int o = 16; o; o >>= 1) s += __shfl_xor_sync(0xffffffffu, s, o);
    if (lane == 0) out[gw] = s + b[0];
}

// ---------------- host: size-based input resolution ----------------
static int pick_by_size(const int* sizes, int n, int want, unsigned char* used)
{
    for (int i = 0; i < n; i++) {
        if (!used[i] && sizes[i] == want) { used[i] = 1; return i; }
    }
    return -1;
}

extern "C" void kernel_launch(void* const* d_in, const int* in_sizes, int n_in,
                              void* d_out, int out_size)
{
    unsigned char used[64];
    for (int i = 0; i < 64; i++) used[i] = 0;
    int ix[24];
    ix[0]  = pick_by_size(in_sizes, n_in, 12582912, used);   // x
    ix[1]  = pick_by_size(in_sizes, n_in, 1179648,  used);   // l1_Wih_f
    ix[2]  = pick_by_size(in_sizes, n_in, 589824,   used);   // l1_Whh_f
    ix[3]  = pick_by_size(in_sizes, n_in, 1536,     used);   // l1_b_f
    ix[4]  = pick_by_size(in_sizes, n_in, 1179648,  used);   // l1_Wih_b
    ix[5]  = pick_by_size(in_sizes, n_in, 589824,   used);   // l1_Whh_b
    ix[6]  = pick_by_size(in_sizes, n_in, 1536,     used);   // l1_b_b
    ix[7]  = pick_by_size(in_sizes, n_in, 294912,   used);   // fc1_W
    ix[8]  = pick_by_size(in_sizes, n_in, 384,      used);   // fc1_b
    ix[9]  = pick_by_size(in_sizes, n_in, 1152,     used);   // attn_W
    ix[10] = pick_by_size(in_sizes, n_in, 1,        used);   // attn_b (unused)
    ix[11] = pick_by_size(in_sizes, n_in, 1179648,  used);   // l2_Wih_f
    ix[12] = pick_by_size(in_sizes, n_in, 589824,   used);   // l2_Whh_f
    ix[13] = pick_by_size(in_sizes, n_in, 1536,     used);   // l2_b_f
    ix[14] = pick_by_size(in_sizes, n_in, 1179648,  used);   // l2_Wih_b
    ix[15] = pick_by_size(in_sizes, n_in, 589824,   used);   // l2_Whh_b
    ix[16] = pick_by_size(in_sizes, n_in, 1536,     used);   // l2_b_b
    ix[17] = pick_by_size(in_sizes, n_in, 98304,    used);   // l2_W1
    ix[18] = pick_by_size(in_sizes, n_in, 256,      used);   // l2_b1
    ix[19] = pick_by_size(in_sizes, n_in, 24576,    used);   // l2_W2
    ix[20] = pick_by_size(in_sizes, n_in, 96,       used);   // l2_b2
    ix[21] = pick_by_size(in_sizes, n_in, 96,       used);   // l2_W3
    ix[22] = pick_by_size(in_sizes, n_in, 1,        used);   // l2_b3
    ix[23] = pick_by_size(in_sizes, n_in, 1,        used);   // window_size

    bool ok = true;
    for (int i = 0; i < 23; i++) if (ix[i] < 0) ok = false;
    if (!ok) {
        for (int i = 0; i < 24; i++) ix[i] = (i < n_in) ? i : -1;
    }

    const float* x      = (const float*)d_in[ix[0]];
    const float* l1Wihf = (const float*)d_in[ix[1]];
    const float* l1Whhf = (const float*)d_in[ix[2]];
    const float* l1bf   = (const float*)d_in[ix[3]];
    const float* l1Wihb = (const float*)d_in[ix[4]];
    const float* l1Whhb = (const float*)d_in[ix[5]];
    const float* l1bb   = (const float*)d_in[ix[6]];
    const float* fc1W   = (const float*)d_in[ix[7]];
    const float* fc1b   = (const float*)d_in[ix[8]];
    const float* attnW  = (const float*)d_in[ix[9]];
    const float* l2Wihf = (const float*)d_in[ix[11]];
    const float* l2Whhf = (const float*)d_in[ix[12]];
    const float* l2bf   = (const float*)d_in[ix[13]];
    const float* l2Wihb = (const float*)d_in[ix[14]];
    const float* l2Whhb = (const float*)d_in[ix[15]];
    const float* l2bb   = (const float*)d_in[ix[16]];
    const float* W1     = (const float*)d_in[ix[17]];
    const float* b1     = (const float*)d_in[ix[18]];
    const float* W2     = (const float*)d_in[ix[19]];
    const float* b2     = (const float*)d_in[ix[20]];
    const float* W3     = (const float*)d_in[ix[21]];
    const float* b3     = (const float*)d_in[ix[22]];
    const int*   wsp    = (ix[23] >= 0) ? (const int*)d_in[ix[23]] : nullptr;

    float *xpF, *xpB, *lstm, *hcat, *h2, *mlp1, *mlp2;
    cudaGetSymbolAddress((void**)&xpF,  g_xprojF);
    cudaGetSymbolAddress((void**)&xpB,  g_xprojB);
    cudaGetSymbolAddress((void**)&lstm, g_lstm);
    cudaGetSymbolAddress((void**)&hcat, g_hcat);
    cudaGetSymbolAddress((void**)&h2,   g_h2);
    cudaGetSymbolAddress((void**)&mlp1, g_mlp1);
    cudaGetSymbolAddress((void**)&mlp2, g_mlp2);

    size_t lsm = (size_t)(RW * WPAD + 16 * WPAD + KSPL * 16 * RW + 16 * NU) * sizeof(float);
    cudaFuncSetAttribute(lstm_scan_kernel,
                         cudaFuncAttributeMaxDynamicSharedMemorySize, (int)lsm);

    // ---- layer 1 ----
    gemm_bias_kernel<0><<<dim3(G4 / 128, M_ / 128), 256>>>(x, l1Wihf, l1bf, xpF, M_, G4, D_, G4);
    gemm_bias_kernel<0><<<dim3(G4 / 128, M_ / 128), 256>>>(x, l1Wihb, l1bb, xpB, M_, G4, D_, G4);
    flags_zero_kernel<<<1, 128>>>();
    lstm_scan_kernel<<<NCTA, TPB, lsm>>>(xpF, xpB, l1Whhf, l1Whhb, lstm);

    // fc1 -> h (stored in first half of hcat, ldc=768)
    gemm_bias_kernel<0><<<dim3(3, M_ / 128), 256>>>(lstm, fc1W, fc1b, hcat, M_, H_, 768, 768);

    // windowed attention -> second half of hcat
    attn_kernel<<<M_ / 8, 256>>>(hcat, attnW, wsp);

    // ---- layer 2 ----
    gemm_bias_kernel<0><<<dim3(G4 / 128, M_ / 128), 256>>>(hcat, l2Wihf, l2bf, xpF, M_, G4, 768, G4);
    gemm_bias_kernel<0><<<dim3(G4 / 128, M_ / 128), 256>>>(hcat, l2Wihb, l2bb, xpB, M_, G4, 768, G4);
    flags_zero_kernel<<<1, 128>>>();
    lstm_scan_kernel<<<NCTA, TPB, lsm>>>(xpF, xpB, l2Whhf, l2Whhb, lstm);

    // fc1 again -> h2
    gemm_bias_kernel<0><<<dim3(3, M_ / 128), 256>>>(lstm, fc1W, fc1b, h2, M_, H_, 768, H_);

    // MLP head
    gemm_bias_kernel<1><<<dim3(2, M_ / 128), 256>>>(h2,   W1, b1, mlp1, M_, 256, H_,  256);
    gemm_bias_kernel<1><<<dim3(1, M_ / 128), 256>>>(mlp1, W2, b2, mlp2, M_, 96,  256, 96);
    gemv_kernel<<<M_ / 8, 256>>>(mlp2, W3, b3, (float*)d_out);
}

// round 4
// speedup vs baseline: 1.2271x; 1.1524x over previous
#include <cuda_runtime.h>
#include <cstdint>
#include <cstddef>

// Problem dims
#define B_   16
#define S_   1024
#define D_   768
#define H_   384
#define G4   1536          // 4*H
#define M_   16384         // B*S

// ---------------- scratch (static device allocations, 256B aligned) ----------------
__device__ __align__(256) float g_xprojF[(size_t)M_ * G4];
__device__ __align__(256) float g_xprojB[(size_t)M_ * G4];
__device__ __align__(256) float g_lstm  [(size_t)M_ * 768];
__device__ __align__(256) float g_hcat  [(size_t)M_ * 768];
__device__ __align__(256) float g_h2    [(size_t)M_ * H_];
__device__ __align__(256) float g_mlp1  [(size_t)M_ * 256];
__device__ __align__(256) float g_mlp2  [(size_t)M_ * 96];
// dataflow step-counters: 128 producers, 32B stride to spread L2 lines
__device__ __align__(256) unsigned g_cnt[128 * 8];

// ---------------- generic GEMM: C = act(A[M,K] @ W[N,K]^T + bias) ----------------
template<int ACT>
__global__ __launch_bounds__(256, 2) void gemm_bias_kernel(
    const float* __restrict__ A, const float* __restrict__ W,
    const float* __restrict__ bias, float* __restrict__ C,
    int M, int N, int K, int ldc)
{
    __shared__ float sA[16][132];
    __shared__ float sB[16][132];
    int tid = threadIdx.x;
    int m0 = blockIdx.y * 128;
    int n0 = blockIdx.x * 128;
    int tx = tid & 15, ty = tid >> 4;

    float acc[8][8];
#pragma unroll
    for (int i = 0; i < 8; i++)
#pragma unroll
        for (int j = 0; j < 8; j++) acc[i][j] = 0.f;

    for (int k0 = 0; k0 < K; k0 += 16) {
#pragma unroll
        for (int e = 0; e < 2; e++) {
            int f4 = tid + 256 * e;
            int r  = f4 >> 2;
            int c4 = (f4 & 3) << 2;
            float4 av = *(const float4*)(A + (size_t)(m0 + r) * K + k0 + c4);
            sA[c4 + 0][r] = av.x; sA[c4 + 1][r] = av.y;
            sA[c4 + 2][r] = av.z; sA[c4 + 3][r] = av.w;
            int n = n0 + r;
            float4 wv = make_float4(0.f, 0.f, 0.f, 0.f);
            if (n < N) wv = *(const float4*)(W + (size_t)n * K + k0 + c4);
            sB[c4 + 0][r] = wv.x; sB[c4 + 1][r] = wv.y;
            sB[c4 + 2][r] = wv.z; sB[c4 + 3][r] = wv.w;
        }
        __syncthreads();
#pragma unroll
        for (int kk = 0; kk < 16; kk++) {
            float a[8], b[8];
            *(float4*)&a[0] = *(const float4*)&sA[kk][ty * 8];
            *(float4*)&a[4] = *(const float4*)&sA[kk][ty * 8 + 4];
            *(float4*)&b[0] = *(const float4*)&sB[kk][tx * 8];
            *(float4*)&b[4] = *(const float4*)&sB[kk][tx * 8 + 4];
#pragma unroll
            for (int i = 0; i < 8; i++)
#pragma unroll
                for (int j = 0; j < 8; j++)
                    acc[i][j] = fmaf(a[i], b[j], acc[i][j]);
        }
        __syncthreads();
    }

#pragma unroll
    for (int i = 0; i < 8; i++) {
        int m = m0 + ty * 8 + i;
#pragma unroll
        for (int j = 0; j < 8; j++) {
            int n = n0 + tx * 8 + j;
            if (n < N) {
                float v = acc[i][j] + bias[n];
                if (ACT) v = fmaxf(v, 0.f);
                C[(size_t)m * ldc + n] = v;
            }
        }
    }
}

// ---------------- LSTM recurrent scan (both directions, persistent) ----------------
// 128 CTAs x 256 threads: dir = cta>>6, group = cta&63, each group owns NU=6 units.
// Release/acquire per-CTA step counters; conflict-free padded smem k-chunks.
#define NU    6
#define RW    24      // 4*NU gate rows per CTA
#define KSPL  16
#define KCH   24      // 384/16 data floats per chunk
#define CHS   28      // padded chunk stride (24 data + 4 pad) -> conflict-free LDS.128
#define RSTR  448     // row stride = KSPL*CHS floats
#define NCTA  128
#define TPB   256

__device__ __forceinline__ float sigm_(float x) { return 1.f / (1.f + __expf(-x)); }
__device__ __forceinline__ float tanh_(float x) {
    float t = __expf(-2.f * fabsf(x));
    float r = (1.f - t) / (1.f + t);
    return x < 0.f ? -r : r;
}

__device__ __forceinline__ void red_release_add(unsigned* p) {
    asm volatile("red.release.gpu.global.add.u32 [%0], %1;" :: "l"(p), "r"(1u) : "memory");
}
__device__ __forceinline__ unsigned ld_acquire(const unsigned* p) {
    unsigned v;
    asm volatile("ld.acquire.gpu.global.u32 %0, [%1];" : "=r"(v) : "l"(p) : "memory");
    return v;
}

// padded offset for k within a row
__device__ __forceinline__ int koff_(int k) { return (k / KCH) * CHS + (k % KCH); }

__global__ void flags_zero_kernel()
{
    g_cnt[threadIdx.x * 8] = 0u;
}

__global__ __launch_bounds__(TPB, 1) void lstm_scan_kernel(
    const float* __restrict__ xpF, const float* __restrict__ xpB,
    const float* __restrict__ WhhF, const float* __restrict__ WhhB,
    float* __restrict__ out /* [B,S,768]: fwd cols 0:384, bwd 384:768 */)
{
    extern __shared__ float sm[];
    float* s_w = sm;                        // RW * RSTR   (10752 fl)
    float* s_h = s_w + RW * RSTR;           // 16 * RSTR   (7168 fl)
    float* s_p = s_h + 16 * RSTR;           // KSPL*16*RW  (6144 fl)
    float* s_c = s_p + KSPL * 16 * RW;      // 16 * NU

    int tid = threadIdx.x;
    int dir = blockIdx.x >> 6;
    int cg  = blockIdx.x & 63;
    int u0  = cg * NU;
    const float* Whh = dir ? WhhB : WhhF;
    const float* xp  = dir ? xpB  : xpF;

    // preload Whh slice into padded layout (rows: gate g, unit u -> local g*NU+u)
    for (int idx = tid; idx < RW * (H_ / 4); idx += TPB) {
        int r  = idx / (H_ / 4);
        int c4 = (idx % (H_ / 4)) * 4;
        int g = r / NU, u = r % NU;
        float4 w = *(const float4*)(Whh + (size_t)(g * H_ + u0 + u) * H_ + c4);
        *(float4*)&s_w[r * RSTR + koff_(c4)] = w;
    }
    if (tid < 16 * NU) s_c[tid] = 0.f;

    int tile = tid >> 4;              // 0..15
    int kq   = tid & 15;              // split-k index
    int b0   = (tile >> 2) << 2;      // {0,4,8,12}
    int r0   = (tile & 3) * NU;       // {0,6,12,18}
    int kpad = kq * CHS;              // padded base offset of this thread's chunk

    int cb = tid / NU, cu = tid % NU; // gate-combine role (tid < 96)

    unsigned* mycnt = &g_cnt[(dir * 64 + cg) * 8];

    for (int step = 0; step < S_; step++) {
        int tt = dir ? (S_ - 1 - step) : step;

        // prefetch xproj for this step's gate combine
        float xpre[4] = {0.f, 0.f, 0.f, 0.f};
        if (tid < 16 * NU) {
            size_t base = ((size_t)(cb * S_ + tt)) * G4 + u0 + cu;
#pragma unroll
            for (int g = 0; g < 4; g++) xpre[g] = __ldg(xp + base + g * H_);
        }

        if (step == 0) {
            for (int idx = tid; idx < 16 * (H_ / 4); idx += TPB) {
                int b = idx / (H_ / 4); int c4 = (idx % (H_ / 4)) * 4;
                *(float4*)&s_h[b * RSTR + koff_(c4)] = make_float4(0.f, 0.f, 0.f, 0.f);
            }
            __syncthreads();
        } else {
            // acquire-wait for all 64 same-direction producers to publish step-1
            if (tid < 64) {
                const unsigned* f = &g_cnt[(dir * 64 + tid) * 8];
                unsigned target = 96u * (unsigned)step;
                while (ld_acquire(f) < target) __nanosleep(20);
            }
            __syncthreads();
            int tp = dir ? (tt + 1) : (tt - 1);
            for (int idx = tid; idx < 16 * (H_ / 4); idx += TPB) {
                int b = idx / (H_ / 4); int c4 = (idx % (H_ / 4)) * 4;
                const float4* src = (const float4*)(out + ((size_t)(b * S_ + tp)) * 768 + dir * H_ + c4);
                *(float4*)&s_h[b * RSTR + koff_(c4)] = __ldcg(src);
            }
            __syncthreads();
        }

        // mini-GEMM: acc[4b][6r] over this thread's 24-float k-chunk (conflict-free)
        float acc[4][NU];
#pragma unroll
        for (int i = 0; i < 4; i++)
#pragma unroll
            for (int j = 0; j < NU; j++) acc[i][j] = 0.f;

#pragma unroll
        for (int k2 = 0; k2 < KCH; k2 += 4) {
            float4 h4[4], w4[NU];
#pragma unroll
            for (int i = 0; i < 4; i++) h4[i] = *(const float4*)&s_h[(b0 + i) * RSTR + kpad + k2];
#pragma unroll
            for (int j = 0; j < NU; j++) w4[j] = *(const float4*)&s_w[(r0 + j) * RSTR + kpad + k2];
#pragma unroll
            for (int i = 0; i < 4; i++)
#pragma unroll
                for (int j = 0; j < NU; j++) {
                    acc[i][j] = fmaf(h4[i].x, w4[j].x, acc[i][j]);
                    acc[i][j] = fmaf(h4[i].y, w4[j].y, acc[i][j]);
                    acc[i][j] = fmaf(h4[i].z, w4[j].z, acc[i][j]);
                    acc[i][j] = fmaf(h4[i].w, w4[j].w, acc[i][j]);
                }
        }
#pragma unroll
        for (int i = 0; i < 4; i++)
#pragma unroll
            for (int j = 0; j < NU; j++)
                s_p[(kq * 16 + b0 + i) * RW + r0 + j] = acc[i][j];
        __syncthreads();

        // gate combine: one thread per (batch, unit); write h + per-thread release
        if (tid < 16 * NU) {
            float gate[4];
#pragma unroll
            for (int g = 0; g < 4; g++) {
                float s = xpre[g];
#pragma unroll
                for (int q = 0; q < KSPL; q++) s += s_p[(q * 16 + cb) * RW + g * NU + cu];
                gate[g] = s;
            }
            float c = sigm_(gate[1]) * s_c[cb * NU + cu] + sigm_(gate[0]) * tanh_(gate[2]);
            s_c[cb * NU + cu] = c;
            float h = sigm_(gate[3]) * tanh_(c);
            __stcg(out + ((size_t)(cb * S_ + tt)) * 768 + dir * H_ + u0 + cu, h);
            red_release_add(mycnt);   // release: my h store visible before count bump
        }
        // no producer-side join needed: consumers wait for count >= 96*(step+1)
    }
}

// ---------------- windowed attention ----------------
__global__ __launch_bounds__(256) void attn_kernel(
    float* __restrict__ hcat, const float* __restrict__ attnW,
    const int* __restrict__ wsp)
{
    int gw   = (int)((blockIdx.x * blockDim.x + threadIdx.x) >> 5);
    int lane = threadIdx.x & 31;
    if (gw >= M_) return;
    int b = gw >> 10, i = gw & 1023;
    int Wn = wsp ? *wsp : 32;
    if (Wn < 0) Wn = 0;
    if (Wn > S_) Wn = S_;

    const float* w2 = attnW + H_;
    const float* w3 = attnW + 2 * H_;
    const float* hi = hcat + (size_t)gw * 768;

    float v[12], a[12];
#pragma unroll
    for (int q = 0; q < 12; q++) {
        int k = q * 32 + lane;
        v[q] = w2[k] + hi[k] * w3[k];
        a[q] = 0.f;
    }
    float m = -1e30f, Z = 0.f;
    int jlo = i - Wn; if (jlo < 0) jlo = 0;
    int jhi = i + Wn; if (jhi > S_ - 1) jhi = S_ - 1;

    for (int j = jlo; j <= jhi; j++) {
        const float* hj = hcat + ((size_t)(b * S_ + j)) * 768;
        float hq[12];
        float s = 0.f;
#pragma unroll
        for (int q = 0; q < 12; q++) {
            hq[q] = hj[q * 32 + lane];
            s = fmaf(v[q], hq[q], s);
        }
#pragma unroll
        for (int o = 16; o; o >>= 1) s += __shfl_xor_sync(0xffffffffu, s, o);
        float mn = fmaxf(m, s);
        float r  = __expf(m - mn);
        float e  = __expf(s - mn);
        Z = Z * r + e;
#pragma unroll
        for (int q = 0; q < 12; q++) a[q] = a[q] * r + e * hq[q];
        m = mn;
    }
    float inv = 1.f / Z;
#pragma unroll
    for (int q = 0; q < 12; q++)
        hcat[(size_t)gw * 768 + H_ + q * 32 + lane] = a[q] * inv;
}

// ---------------- final gemv: out[m] = y2[m,:96] @ W3 + b3 ----------------
__global__ __launch_bounds__(256) void gemv_kernel(
    const float* __restrict__ A, const float* __restrict__ w,
    const float* __restrict__ b, float* __restrict__ out)
{
    int gw   = (int)((blockIdx.x * blockDim.x + threadIdx.x) >> 5);
    int lane = threadIdx.x & 31;
    if (gw >= M_) return;
    float s = 0.f;
#pragma unroll
    for (int k = lane; k < 96; k += 32) s = fmaf(A[(size_t)gw * 96 + k], w[k], s);
#pragma unroll
    for (int o = 16; o; o >>= 1) s += __shfl_xor_sync(0xffffffffu, s, o);
    if (lane == 0) out[gw] = s + b[0];
}

// ---------------- host: size-based input resolution ----------------
static int pick_by_size(const int* sizes, int n, int want, unsigned char* used)
{
    for (int i = 0; i < n; i++) {
        if (!used[i] && sizes[i] == want) { used[i] = 1; return i; }
    }
    return -1;
}

extern "C" void kernel_launch(void* const* d_in, const int* in_sizes, int n_in,
                              void* d_out, int out_size)
{
    unsigned char used[64];
    for (int i = 0; i < 64; i++) used[i] = 0;
    int ix[24];
    ix[0]  = pick_by_size(in_sizes, n_in, 12582912, used);   // x
    ix[1]  = pick_by_size(in_sizes, n_in, 1179648,  used);   // l1_Wih_f
    ix[2]  = pick_by_size(in_sizes, n_in, 589824,   used);   // l1_Whh_f
    ix[3]  = pick_by_size(in_sizes, n_in, 1536,     used);   // l1_b_f
    ix[4]  = pick_by_size(in_sizes, n_in, 1179648,  used);   // l1_Wih_b
    ix[5]  = pick_by_size(in_sizes, n_in, 589824,   used);   // l1_Whh_b
    ix[6]  = pick_by_size(in_sizes, n_in, 1536,     used);   // l1_b_b
    ix[7]  = pick_by_size(in_sizes, n_in, 294912,   used);   // fc1_W
    ix[8]  = pick_by_size(in_sizes, n_in, 384,      used);   // fc1_b
    ix[9]  = pick_by_size(in_sizes, n_in, 1152,     used);   // attn_W
    ix[10] = pick_by_size(in_sizes, n_in, 1,        used);   // attn_b (unused)
    ix[11] = pick_by_size(in_sizes, n_in, 1179648,  used);   // l2_Wih_f
    ix[12] = pick_by_size(in_sizes, n_in, 589824,   used);   // l2_Whh_f
    ix[13] = pick_by_size(in_sizes, n_in, 1536,     used);   // l2_b_f
    ix[14] = pick_by_size(in_sizes, n_in, 1179648,  used);   // l2_Wih_b
    ix[15] = pick_by_size(in_sizes, n_in, 589824,   used);   // l2_Whh_b
    ix[16] = pick_by_size(in_sizes, n_in, 1536,     used);   // l2_b_b
    ix[17] = pick_by_size(in_sizes, n_in, 98304,    used);   // l2_W1
    ix[18] = pick_by_size(in_sizes, n_in, 256,      used);   // l2_b1
    ix[19] = pick_by_size(in_sizes, n_in, 24576,    used);   // l2_W2
    ix[20] = pick_by_size(in_sizes, n_in, 96,       used);   // l2_b2
    ix[21] = pick_by_size(in_sizes, n_in, 96,       used);   // l2_W3
    ix[22] = pick_by_size(in_sizes, n_in, 1,        used);   // l2_b3
    ix[23] = pick_by_size(in_sizes, n_in, 1,        used);   // window_size

    bool ok = true;
    for (int i = 0; i < 23; i++) if (ix[i] < 0) ok = false;
    if (!ok) {
        for (int i = 0; i < 24; i++) ix[i] = (i < n_in) ? i : -1;
    }

    const float* x      = (const float*)d_in[ix[0]];
    const float* l1Wihf = (const float*)d_in[ix[1]];
    const float* l1Whhf = (const float*)d_in[ix[2]];
    const float* l1bf   = (const float*)d_in[ix[3]];
    const float* l1Wihb = (const float*)d_in[ix[4]];
    const float* l1Whhb = (const float*)d_in[ix[5]];
    const float* l1bb   = (const float*)d_in[ix[6]];
    const float* fc1W   = (const float*)d_in[ix[7]];
    const float* fc1b   = (const float*)d_in[ix[8]];
    const float* attnW  = (const float*)d_in[ix[9]];
    const float* l2Wihf = (const float*)d_in[ix[11]];
    const float* l2Whhf = (const float*)d_in[ix[12]];
    const float* l2bf   = (const float*)d_in[ix[13]];
    const float* l2Wihb = (const float*)d_in[ix[14]];
    const float* l2Whhb = (const float*)d_in[ix[15]];
    const float* l2bb   = (const float*)d_in[ix[16]];
    const float* W1     = (const float*)d_in[ix[17]];
    const float* b1     = (const float*)d_in[ix[18]];
    const float* W2     = (const float*)d_in[ix[19]];
    const float* b2     = (const float*)d_in[ix[20]];
    const float* W3     = (const float*)d_in[ix[21]];
    const float* b3     = (const float*)d_in[ix[22]];
    const int*   wsp    = (ix[23] >= 0) ? (const int*)d_in[ix[23]] : nullptr;

    float *xpF, *xpB, *lstm, *hcat, *h2, *mlp1, *mlp2;
    cudaGetSymbolAddress((void**)&xpF,  g_xprojF);
    cudaGetSymbolAddress((void**)&xpB,  g_xprojB);
    cudaGetSymbolAddress((void**)&lstm, g_lstm);
    cudaGetSymbolAddress((void**)&hcat, g_hcat);
    cudaGetSymbolAddress((void**)&h2,   g_h2);
    cudaGetSymbolAddress((void**)&mlp1, g_mlp1);
    cudaGetSymbolAddress((void**)&mlp2, g_mlp2);

    size_t lsm = (size_t)(RW * RSTR + 16 * RSTR + KSPL * 16 * RW + 16 * NU) * sizeof(float);
    cudaFuncSetAttribute(lstm_scan_kernel,
                         cudaFuncAttributeMaxDynamicSharedMemorySize, (int)lsm);

    // ---- layer 1 ----
    gemm_bias_kernel<0><<<dim3(G4 / 128, M_ / 128), 256>>>(x, l1Wihf, l1bf, xpF, M_, G4, D_, G4);
    gemm_bias_kernel<0><<<dim3(G4 / 128, M_ / 128), 256>>>(x, l1Wihb, l1bb, xpB, M_, G4, D_, G4);
    flags_zero_kernel<<<1, 128>>>();
    lstm_scan_kernel<<<NCTA, TPB, lsm>>>(xpF, xpB, l1Whhf, l1Whhb, lstm);

    // fc1 -> h (stored in first half of hcat, ldc=768)
    gemm_bias_kernel<0><<<dim3(3, M_ / 128), 256>>>(lstm, fc1W, fc1b, hcat, M_, H_, 768, 768);

    // windowed attention -> second half of hcat
    attn_kernel<<<M_ / 8, 256>>>(hcat, attnW, wsp);

    // ---- layer 2 ----
    gemm_bias_kernel<0><<<dim3(G4 / 128, M_ / 128), 256>>>(hcat, l2Wihf, l2bf, xpF, M_, G4, 768, G4);
    gemm_bias_kernel<0><<<dim3(G4 / 128, M_ / 128), 256>>>(hcat, l2Wihb, l2bb, xpB, M_, G4, 768, G4);
    flags_zero_kernel<<<1, 128>>>();
    lstm_scan_kernel<<<NCTA, TPB, lsm>>>(xpF, xpB, l2Whhf, l2Whhb, lstm);

    // fc1 again -> h2
    gemm_bias_kernel<0><<<dim3(3, M_ / 128), 256>>>(lstm, fc1W, fc1b, h2, M_, H_, 768, H_);

    // MLP head
    gemm_bias_kernel<1><<<dim3(2, M_ / 128), 256>>>(h2,   W1, b1, mlp1, M_, 256, H_,  256);
    gemm_bias_kernel<1><<<dim3(1, M_ / 128), 256>>>(mlp1, W2, b2, mlp2, M_, 96,  256, 96);
    gemv_kernel<<<M_ / 8, 256>>>(mlp2, W3, b3, (float*)d_out);
}

// round 5
// speedup vs baseline: 1.2464x; 1.0157x over previous
#include <cuda_runtime.h>
#include <cstdint>
#include <cstddef>

// Problem dims
#define B_   16
#define S_   1024
#define D_   768
#define H_   384
#define G4   1536          // 4*H
#define M_   16384         // B*S

// ---------------- scratch (static device allocations, 256B aligned) ----------------
__device__ __align__(256) float g_xprojF[(size_t)M_ * G4];
__device__ __align__(256) float g_xprojB[(size_t)M_ * G4];
__device__ __align__(256) float g_lstm  [(size_t)M_ * 768];
__device__ __align__(256) float g_hcat  [(size_t)M_ * 768];
__device__ __align__(256) float g_h2    [(size_t)M_ * H_];
__device__ __align__(256) float g_mlp1  [(size_t)M_ * 256];
__device__ __align__(256) float g_mlp2  [(size_t)M_ * 96];
// dataflow step-counters: 128 producers, 32B stride to spread L2 lines
__device__ __align__(256) unsigned g_cnt[128 * 8];

// ---------------- packed f32x2 helpers ----------------
__device__ __forceinline__ void fma2_(unsigned long long& d,
                                      unsigned long long a,
                                      unsigned long long b) {
    asm("fma.rn.f32x2 %0, %1, %2, %0;" : "+l"(d) : "l"(a), "l"(b));
}
__device__ __forceinline__ unsigned long long pack2_(float x, float y) {
    unsigned long long d;
    asm("mov.b64 %0, {%1, %2};" : "=l"(d) : "f"(x), "f"(y));
    return d;
}
__device__ __forceinline__ float2 unpack2_(unsigned long long v) {
    float2 r;
    asm("mov.b64 {%0, %1}, %2;" : "=f"(r.x), "=f"(r.y) : "l"(v));
    return r;
}

// ---------------- generic GEMM: C = act(A[M,K] @ W[N,K]^T + bias) ----------------
// 128x128 tile, BK=16, 256 threads, 8x8 per thread, f32x2 packed inner loop.
template<int ACT>
__global__ __launch_bounds__(256, 2) void gemm_bias_kernel(
    const float* __restrict__ A, const float* __restrict__ W,
    const float* __restrict__ bias, float* __restrict__ C,
    int M, int N, int K, int ldc)
{
    __shared__ float sA[16][132];
    __shared__ float sB[16][132];
    int tid = threadIdx.x;
    int m0 = blockIdx.y * 128;
    int n0 = blockIdx.x * 128;
    int tx = tid & 15, ty = tid >> 4;

    unsigned long long acc2[8][4];   // [i][j2], each packs (j=2*j2, 2*j2+1)
#pragma unroll
    for (int i = 0; i < 8; i++)
#pragma unroll
        for (int j = 0; j < 4; j++) acc2[i][j] = 0ULL;

    for (int k0 = 0; k0 < K; k0 += 16) {
#pragma unroll
        for (int e = 0; e < 2; e++) {
            int f4 = tid + 256 * e;
            int r  = f4 >> 2;
            int c4 = (f4 & 3) << 2;
            float4 av = *(const float4*)(A + (size_t)(m0 + r) * K + k0 + c4);
            sA[c4 + 0][r] = av.x; sA[c4 + 1][r] = av.y;
            sA[c4 + 2][r] = av.z; sA[c4 + 3][r] = av.w;
            int n = n0 + r;
            float4 wv = make_float4(0.f, 0.f, 0.f, 0.f);
            if (n < N) wv = *(const float4*)(W + (size_t)n * K + k0 + c4);
            sB[c4 + 0][r] = wv.x; sB[c4 + 1][r] = wv.y;
            sB[c4 + 2][r] = wv.z; sB[c4 + 3][r] = wv.w;
        }
        __syncthreads();
#pragma unroll
        for (int kk = 0; kk < 16; kk++) {
            float a[8];
            *(float4*)&a[0] = *(const float4*)&sA[kk][ty * 8];
            *(float4*)&a[4] = *(const float4*)&sA[kk][ty * 8 + 4];
            ulonglong2 bv0 = *(const ulonglong2*)&sB[kk][tx * 8];
            ulonglong2 bv1 = *(const ulonglong2*)&sB[kk][tx * 8 + 4];
            unsigned long long b2[4] = {bv0.x, bv0.y, bv1.x, bv1.y};
#pragma unroll
            for (int i = 0; i < 8; i++) {
                unsigned long long a2 = pack2_(a[i], a[i]);
#pragma unroll
                for (int j = 0; j < 4; j++)
                    fma2_(acc2[i][j], a2, b2[j]);
            }
        }
        __syncthreads();
    }

#pragma unroll
    for (int i = 0; i < 8; i++) {
        int m = m0 + ty * 8 + i;
#pragma unroll
        for (int j2 = 0; j2 < 4; j2++) {
            float2 p = unpack2_(acc2[i][j2]);
            int n = n0 + tx * 8 + j2 * 2;
            if (n < N) {
                float v0 = p.x + bias[n];
                if (ACT) v0 = fmaxf(v0, 0.f);
                C[(size_t)m * ldc + n] = v0;
            }
            if (n + 1 < N) {
                float v1 = p.y + bias[n + 1];
                if (ACT) v1 = fmaxf(v1, 0.f);
                C[(size_t)m * ldc + n + 1] = v1;
            }
        }
    }
}

// ---------------- LSTM recurrent scan (both directions, persistent) ----------------
#define NU    6
#define RW    24      // 4*NU gate rows per CTA
#define KSPL  16
#define KCH   24      // 384/16 data floats per chunk
#define CHS   28      // padded chunk stride -> conflict-free LDS.128
#define RSTR  448     // row stride = KSPL*CHS floats
#define NCTA  128
#define TPB   256

__device__ __forceinline__ float sigm_(float x) { return 1.f / (1.f + __expf(-x)); }
__device__ __forceinline__ float tanh_(float x) {
    float t = __expf(-2.f * fabsf(x));
    float r = (1.f - t) / (1.f + t);
    return x < 0.f ? -r : r;
}

__device__ __forceinline__ void red_release_add(unsigned* p) {
    asm volatile("red.release.gpu.global.add.u32 [%0], %1;" :: "l"(p), "r"(1u) : "memory");
}
__device__ __forceinline__ unsigned ld_acquire(const unsigned* p) {
    unsigned v;
    asm volatile("ld.acquire.gpu.global.u32 %0, [%1];" : "=r"(v) : "l"(p) : "memory");
    return v;
}

__device__ __forceinline__ int koff_(int k) { return (k / KCH) * CHS + (k % KCH); }

__global__ void flags_zero_kernel()
{
    g_cnt[threadIdx.x * 8] = 0u;
}

__global__ __launch_bounds__(TPB, 1) void lstm_scan_kernel(
    const float* __restrict__ xpF, const float* __restrict__ xpB,
    const float* __restrict__ WhhF, const float* __restrict__ WhhB,
    float* __restrict__ out /* [B,S,768]: fwd cols 0:384, bwd 384:768 */)
{
    extern __shared__ float sm[];
    float* s_w = sm;                        // RW * RSTR
    float* s_h = s_w + RW * RSTR;           // 16 * RSTR
    float* s_p = s_h + 16 * RSTR;           // KSPL*16*RW
    float* s_c = s_p + KSPL * 16 * RW;      // 16 * NU

    int tid = threadIdx.x;
    int dir = blockIdx.x >> 6;
    int cg  = blockIdx.x & 63;
    int u0  = cg * NU;
    const float* Whh = dir ? WhhB : WhhF;
    const float* xp  = dir ? xpB  : xpF;

    // preload Whh slice into padded layout
    for (int idx = tid; idx < RW * (H_ / 4); idx += TPB) {
        int r  = idx / (H_ / 4);
        int c4 = (idx % (H_ / 4)) * 4;
        int g = r / NU, u = r % NU;
        float4 w = *(const float4*)(Whh + (size_t)(g * H_ + u0 + u) * H_ + c4);
        *(float4*)&s_w[r * RSTR + koff_(c4)] = w;
    }
    if (tid < 16 * NU) s_c[tid] = 0.f;

    int tile = tid >> 4;              // 0..15
    int kq   = tid & 15;              // split-k index
    int b0   = (tile >> 2) << 2;      // {0,4,8,12}
    int r0   = (tile & 3) * NU;       // {0,6,12,18}
    int kpad = kq * CHS;

    int cb = tid / NU, cu = tid % NU; // gate-combine role (tid < 96)

    unsigned* mycnt = &g_cnt[(dir * 64 + cg) * 8];

    for (int step = 0; step < S_; step++) {
        int tt = dir ? (S_ - 1 - step) : step;

        // prefetch xproj for this step's gate combine
        float xpre[4] = {0.f, 0.f, 0.f, 0.f};
        if (tid < 16 * NU) {
            size_t base = ((size_t)(cb * S_ + tt)) * G4 + u0 + cu;
#pragma unroll
            for (int g = 0; g < 4; g++) xpre[g] = __ldg(xp + base + g * H_);
        }

        if (step == 0) {
            for (int idx = tid; idx < 16 * (H_ / 4); idx += TPB) {
                int b = idx / (H_ / 4); int c4 = (idx % (H_ / 4)) * 4;
                *(float4*)&s_h[b * RSTR + koff_(c4)] = make_float4(0.f, 0.f, 0.f, 0.f);
            }
            __syncthreads();
        } else {
            if (tid < 64) {
                const unsigned* f = &g_cnt[(dir * 64 + tid) * 8];
                unsigned target = 96u * (unsigned)step;
                while (ld_acquire(f) < target) __nanosleep(20);
            }
            __syncthreads();
            int tp = dir ? (tt + 1) : (tt - 1);
            for (int idx = tid; idx < 16 * (H_ / 4); idx += TPB) {
                int b = idx / (H_ / 4); int c4 = (idx % (H_ / 4)) * 4;
                const float4* src = (const float4*)(out + ((size_t)(b * S_ + tp)) * 768 + dir * H_ + c4);
                *(float4*)&s_h[b * RSTR + koff_(c4)] = __ldcg(src);
            }
            __syncthreads();
        }

        // mini-GEMM (f32x2 packed): acc2[4b][6r] over this thread's 24-float chunk
        unsigned long long acc2[4][NU];
#pragma unroll
        for (int i = 0; i < 4; i++)
#pragma unroll
            for (int j = 0; j < NU; j++) acc2[i][j] = 0ULL;

#pragma unroll
        for (int k2 = 0; k2 < KCH; k2 += 4) {
            ulonglong2 hv[4], wv[NU];
#pragma unroll
            for (int i = 0; i < 4; i++)
                hv[i] = *(const ulonglong2*)&s_h[(b0 + i) * RSTR + kpad + k2];
#pragma unroll
            for (int j = 0; j < NU; j++)
                wv[j] = *(const ulonglong2*)&s_w[(r0 + j) * RSTR + kpad + k2];
#pragma unroll
            for (int i = 0; i < 4; i++)
#pragma unroll
                for (int j = 0; j < NU; j++) {
                    fma2_(acc2[i][j], hv[i].x, wv[j].x);
                    fma2_(acc2[i][j], hv[i].y, wv[j].y);
                }
        }
#pragma unroll
        for (int i = 0; i < 4; i++)
#pragma unroll
            for (int j = 0; j < NU; j++) {
                float2 p = unpack2_(acc2[i][j]);
                s_p[(kq * 16 + b0 + i) * RW + r0 + j] = p.x + p.y;
            }
        __syncthreads();

        // gate combine: one thread per (batch, unit); write h + per-thread release
        if (tid < 16 * NU) {
            float gate[4];
#pragma unroll
            for (int g = 0; g < 4; g++) {
                float s = xpre[g];
#pragma unroll
                for (int q = 0; q < KSPL; q++) s += s_p[(q * 16 + cb) * RW + g * NU + cu];
                gate[g] = s;
            }
            float c = sigm_(gate[1]) * s_c[cb * NU + cu] + sigm_(gate[0]) * tanh_(gate[2]);
            s_c[cb * NU + cu] = c;
            float h = sigm_(gate[3]) * tanh_(c);
            __stcg(out + ((size_t)(cb * S_ + tt)) * 768 + dir * H_ + u0 + cu, h);
            red_release_add(mycnt);
        }
    }
}

// ---------------- windowed attention ----------------
__global__ __launch_bounds__(256) void attn_kernel(
    float* __restrict__ hcat, const float* __restrict__ attnW,
    const int* __restrict__ wsp)
{
    int gw   = (int)((blockIdx.x * blockDim.x + threadIdx.x) >> 5);
    int lane = threadIdx.x & 31;
    if (gw >= M_) return;
    int b = gw >> 10, i = gw & 1023;
    int Wn = wsp ? *wsp : 32;
    if (Wn < 0) Wn = 0;
    if (Wn > S_) Wn = S_;

    const float* w2 = attnW + H_;
    const float* w3 = attnW + 2 * H_;
    const float* hi = hcat + (size_t)gw * 768;

    float v[12], a[12];
#pragma unroll
    for (int q = 0; q < 12; q++) {
        int k = q * 32 + lane;
        v[q] = w2[k] + hi[k] * w3[k];
        a[q] = 0.f;
    }
    float m = -1e30f, Z = 0.f;
    int jlo = i - Wn; if (jlo < 0) jlo = 0;
    int jhi = i + Wn; if (jhi > S_ - 1) jhi = S_ - 1;

    for (int j = jlo; j <= jhi; j++) {
        const float* hj = hcat + ((size_t)(b * S_ + j)) * 768;
        float hq[12];
        float s = 0.f;
#pragma unroll
        for (int q = 0; q < 12; q++) {
            hq[q] = hj[q * 32 + lane];
            s = fmaf(v[q], hq[q], s);
        }
#pragma unroll
        for (int o = 16; o; o >>= 1) s += __shfl_xor_sync(0xffffffffu, s, o);
        float mn = fmaxf(m, s);
        float r  = __expf(m - mn);
        float e  = __expf(s - mn);
        Z = Z * r + e;
#pragma unroll
        for (int q = 0; q < 12; q++) a[q] = a[q] * r + e * hq[q];
        m = mn;
    }
    float inv = 1.f / Z;
#pragma unroll
    for (int q = 0; q < 12; q++)
        hcat[(size_t)gw * 768 + H_ + q * 32 + lane] = a[q] * inv;
}

// ---------------- final gemv: out[m] = y2[m,:96] @ W3 + b3 ----------------
__global__ __launch_bounds__(256) void gemv_kernel(
    const float* __restrict__ A, const float* __restrict__ w,
    const float* __restrict__ b, float* __restrict__ out)
{
    int gw   = (int)((blockIdx.x * blockDim.x + threadIdx.x) >> 5);
    int lane = threadIdx.x & 31;
    if (gw >= M_) return;
    float s = 0.f;
#pragma unroll
    for (int k = lane; k < 96; k += 32) s = fmaf(A[(size_t)gw * 96 + k], w[k], s);
#pragma unroll
    for (int o = 16; o; o >>= 1) s += __shfl_xor_sync(0xffffffffu, s, o);
    if (lane == 0) out[gw] = s + b[0];
}

// ---------------- host: size-based input resolution ----------------
static int pick_by_size(const int* sizes, int n, int want, unsigned char* used)
{
    for (int i = 0; i < n; i++) {
        if (!used[i] && sizes[i] == want) { used[i] = 1; return i; }
    }
    return -1;
}

extern "C" void kernel_launch(void* const* d_in, const int* in_sizes, int n_in,
                              void* d_out, int out_size)
{
    unsigned char used[64];
    for (int i = 0; i < 64; i++) used[i] = 0;
    int ix[24];
    ix[0]  = pick_by_size(in_sizes, n_in, 12582912, used);   // x
    ix[1]  = pick_by_size(in_sizes, n_in, 1179648,  used);   // l1_Wih_f
    ix[2]  = pick_by_size(in_sizes, n_in, 589824,   used);   // l1_Whh_f
    ix[3]  = pick_by_size(in_sizes, n_in, 1536,     used);   // l1_b_f
    ix[4]  = pick_by_size(in_sizes, n_in, 1179648,  used);   // l1_Wih_b
    ix[5]  = pick_by_size(in_sizes, n_in, 589824,   used);   // l1_Whh_b
    ix[6]  = pick_by_size(in_sizes, n_in, 1536,     used);   // l1_b_b
    ix[7]  = pick_by_size(in_sizes, n_in, 294912,   used);   // fc1_W
    ix[8]  = pick_by_size(in_sizes, n_in, 384,      used);   // fc1_b
    ix[9]  = pick_by_size(in_sizes, n_in, 1152,     used);   // attn_W
    ix[10] = pick_by_size(in_sizes, n_in, 1,        used);   // attn_b (unused)
    ix[11] = pick_by_size(in_sizes, n_in, 1179648,  used);   // l2_Wih_f
    ix[12] = pick_by_size(in_sizes, n_in, 589824,   used);   // l2_Whh_f
    ix[13] = pick_by_size(in_sizes, n_in, 1536,     used);   // l2_b_f
    ix[14] = pick_by_size(in_sizes, n_in, 1179648,  used);   // l2_Wih_b
    ix[15] = pick_by_size(in_sizes, n_in, 589824,   used);   // l2_Whh_b
    ix[16] = pick_by_size(in_sizes, n_in, 1536,     used);   // l2_b_b
    ix[17] = pick_by_size(in_sizes, n_in, 98304,    used);   // l2_W1
    ix[18] = pick_by_size(in_sizes, n_in, 256,      used);   // l2_b1
    ix[19] = pick_by_size(in_sizes, n_in, 24576,    used);   // l2_W2
    ix[20] = pick_by_size(in_sizes, n_in, 96,       used);   // l2_b2
    ix[21] = pick_by_size(in_sizes, n_in, 96,       used);   // l2_W3
    ix[22] = pick_by_size(in_sizes, n_in, 1,        used);   // l2_b3
    ix[23] = pick_by_size(in_sizes, n_in, 1,        used);   // window_size

    bool ok = true;
    for (int i = 0; i < 23; i++) if (ix[i] < 0) ok = false;
    if (!ok) {
        for (int i = 0; i < 24; i++) ix[i] = (i < n_in) ? i : -1;
    }

    const float* x      = (const float*)d_in[ix[0]];
    const float* l1Wihf = (const float*)d_in[ix[1]];
    const float* l1Whhf = (const float*)d_in[ix[2]];
    const float* l1bf   = (const float*)d_in[ix[3]];
    const float* l1Wihb = (const float*)d_in[ix[4]];
    const float* l1Whhb = (const float*)d_in[ix[5]];
    const float* l1bb   = (const float*)d_in[ix[6]];
    const float* fc1W   = (const float*)d_in[ix[7]];
    const float* fc1b   = (const float*)d_in[ix[8]];
    const float* attnW  = (const float*)d_in[ix[9]];
    const float* l2Wihf = (const float*)d_in[ix[11]];
    const float* l2Whhf = (const float*)d_in[ix[12]];
    const float* l2bf   = (const float*)d_in[ix[13]];
    const float* l2Wihb = (const float*)d_in[ix[14]];
    const float* l2Whhb = (const float*)d_in[ix[15]];
    const float* l2bb   = (const float*)d_in[ix[16]];
    const float* W1     = (const float*)d_in[ix[17]];
    const float* b1     = (const float*)d_in[ix[18]];
    const float* W2     = (const float*)d_in[ix[19]];
    const float* b2     = (const float*)d_in[ix[20]];
    const float* W3     = (const float*)d_in[ix[21]];
    const float* b3     = (const float*)d_in[ix[22]];
    const int*   wsp    = (ix[23] >= 0) ? (const int*)d_in[ix[23]] : nullptr;

    float *xpF, *xpB, *lstm, *hcat, *h2, *mlp1, *mlp2;
    cudaGetSymbolAddress((void**)&xpF,  g_xprojF);
    cudaGetSymbolAddress((void**)&xpB,  g_xprojB);
    cudaGetSymbolAddress((void**)&lstm, g_lstm);
    cudaGetSymbolAddress((void**)&hcat, g_hcat);
    cudaGetSymbolAddress((void**)&h2,   g_h2);
    cudaGetSymbolAddress((void**)&mlp1, g_mlp1);
    cudaGetSymbolAddress((void**)&mlp2, g_mlp2);

    size_t lsm = (size_t)(RW * RSTR + 16 * RSTR + KSPL * 16 * RW + 16 * NU) * sizeof(float);
    cudaFuncSetAttribute(lstm_scan_kernel,
                         cudaFuncAttributeMaxDynamicSharedMemorySize, (int)lsm);

    // ---- layer 1 ----
    gemm_bias_kernel<0><<<dim3(G4 / 128, M_ / 128), 256>>>(x, l1Wihf, l1bf, xpF, M_, G4, D_, G4);
    gemm_bias_kernel<0><<<dim3(G4 / 128, M_ / 128), 256>>>(x, l1Wihb, l1bb, xpB, M_, G4, D_, G4);
    flags_zero_kernel<<<1, 128>>>();
    lstm_scan_kernel<<<NCTA, TPB, lsm>>>(xpF, xpB, l1Whhf, l1Whhb, lstm);

    // fc1 -> h (stored in first half of hcat, ldc=768)
    gemm_bias_kernel<0><<<dim3(3, M_ / 128), 256>>>(lstm, fc1W, fc1b, hcat, M_, H_, 768, 768);

    // windowed attention -> second half of hcat
    attn_kernel<<<M_ / 8, 256>>>(hcat, attnW, wsp);

    // ---- layer 2 ----
    gemm_bias_kernel<0><<<dim3(G4 / 128, M_ / 128), 256>>>(hcat, l2Wihf, l2bf, xpF, M_, G4, 768, G4);
    gemm_bias_kernel<0><<<dim3(G4 / 128, M_ / 128), 256>>>(hcat, l2Wihb, l2bb, xpB, M_, G4, 768, G4);
    flags_zero_kernel<<<1, 128>>>();
    lstm_scan_kernel<<<NCTA, TPB, lsm>>>(xpF, xpB, l2Whhf, l2Whhb, lstm);

    // fc1 again -> h2
    gemm_bias_kernel<0><<<dim3(3, M_ / 128), 256>>>(lstm, fc1W, fc1b, h2, M_, H_, 768, H_);

    // MLP head
    gemm_bias_kernel<1><<<dim3(2, M_ / 128), 256>>>(h2,   W1, b1, mlp1, M_, 256, H_,  256);
    gemm_bias_kernel<1><<<dim3(1, M_ / 128), 256>>>(mlp1, W2, b2, mlp2, M_, 96,  256, 96);
    gemv_kernel<<<M_ / 8, 256>>>(mlp2, W3, b3, (float*)d_out);
}